// round 2
// baseline (speedup 1.0000x reference)
#include <cuda_runtime.h>
#include <stdint.h>

#define COLS 16384
#define NTHREADS 512
#define VEC (COLS / 4 / NTHREADS)   // 8 float4 per thread

// Monotonic float->uint key transform (order-preserving for all finite floats)
__device__ __forceinline__ uint32_t f2k(float f) {
    uint32_t u = __float_as_uint(f);
    return u ^ ((uint32_t)((int32_t)u >> 31) | 0x80000000u);
}
__device__ __forceinline__ float k2f(uint32_t k) {
    uint32_t mask = (~((uint32_t)((int32_t)k >> 31))) | 0x80000000u;
    return __uint_as_float(k ^ mask);
}

// Find highest bin b such that count(keys in bins > b) < kneed <= count(bins >= b).
// hist[NBINS] valid on entry. Writes ctrl[0]=b, ctrl[1]=count strictly above b,
// ctrl[2]=hist[b] (count inside the winning bin).
// All 512 threads must participate. Ends with __syncthreads.
template <int NBINS>
__device__ void select_bin(int* hist, int* S, int* ctrl, int kneed) {
    const int CH = (NBINS / 512 > 0) ? (NBINS / 512) : 1;
    const int NC = NBINS / CH;
    int t = threadIdx.x;

    int cs = 0;
    if (t < NC) {
#pragma unroll
        for (int j = 0; j < CH; j++) cs += hist[t * CH + j];
    }
    S[t] = cs;
    __syncthreads();
    // inclusive suffix sum over 512 entries (Hillis-Steele)
    for (int off = 1; off < 512; off <<= 1) {
        int v = (t + off < 512) ? S[t + off] : 0;
        __syncthreads();
        S[t] += v;
        __syncthreads();
    }
    int Sown  = S[t];
    int Snext = (t < 511) ? S[t + 1] : 0;
    if (t < NC && Sown >= kneed && Snext < kneed) {
        int c = Snext;
        int b = t * CH;
        int hb = 0;
        for (int j = CH - 1; j >= 0; j--) {
            int h = hist[t * CH + j];
            if (c + h >= kneed) { b = t * CH + j; hb = h; break; }
            c += h;
        }
        ctrl[0] = b;
        ctrl[1] = c;
        ctrl[2] = hb;
    }
    __syncthreads();
}

__global__ void __launch_bounds__(NTHREADS, 2)
topk_scatter_kernel(const float* __restrict__ x, const int* __restrict__ kp,
                    float* __restrict__ out) {
    extern __shared__ uint8_t sm[];
    uint32_t* keys = (uint32_t*)sm;                 // 16384 keys  (64 KB)
    int* hist = (int*)(sm + COLS * 4);              // 4096 bins   (16 KB) — reused as tie list
    int* S    = hist + 4096;                        // 512 scan    (2 KB)
    int* ctrl = S + 512;                            // [0] bin, [1] c_above, [2] bin count, [3] idx_cut

    const int t   = threadIdx.x;
    const int row = blockIdx.x;
    const float4* xr = (const float4*)(x + (size_t)row * COLS);
    uint4* k4 = (uint4*)keys;

    // ---- load row from GMEM, transform to monotonic keys, stash in SMEM ----
#pragma unroll
    for (int i = 0; i < VEC; i++) {
        float4 v = xr[i * NTHREADS + t];
        uint4 kk;
        kk.x = f2k(v.x); kk.y = f2k(v.y); kk.z = f2k(v.z); kk.w = f2k(v.w);
        k4[i * NTHREADS + t] = kk;
    }
    const int K = *kp;

    // ---- pass 1: top 12 bits ----
    for (int i = t; i < 4096; i += NTHREADS) hist[i] = 0;
    __syncthreads();
#pragma unroll
    for (int i = 0; i < VEC; i++) {
        uint4 kk = k4[i * NTHREADS + t];
        atomicAdd(&hist[kk.x >> 20], 1);
        atomicAdd(&hist[kk.y >> 20], 1);
        atomicAdd(&hist[kk.z >> 20], 1);
        atomicAdd(&hist[kk.w >> 20], 1);
    }
    __syncthreads();
    select_bin<4096>(hist, S, ctrl, K);
    const uint32_t b1 = (uint32_t)ctrl[0];
    const int c1 = ctrl[1];
    int kneed = K - c1;
    int cgt = c1;
    __syncthreads();   // everyone has read ctrl before it is reused

    // ---- pass 2: middle 12 bits (restricted to bin b1) ----
    for (int i = t; i < 4096; i += NTHREADS) hist[i] = 0;
    __syncthreads();
#pragma unroll
    for (int i = 0; i < VEC; i++) {
        uint4 kk = k4[i * NTHREADS + t];
        if ((kk.x >> 20) == b1) atomicAdd(&hist[(kk.x >> 8) & 0xFFF], 1);
        if ((kk.y >> 20) == b1) atomicAdd(&hist[(kk.y >> 8) & 0xFFF], 1);
        if ((kk.z >> 20) == b1) atomicAdd(&hist[(kk.z >> 8) & 0xFFF], 1);
        if ((kk.w >> 20) == b1) atomicAdd(&hist[(kk.w >> 8) & 0xFFF], 1);
    }
    __syncthreads();
    select_bin<4096>(hist, S, ctrl, kneed);
    const uint32_t b2 = (uint32_t)ctrl[0];
    const int c2 = ctrl[1];
    kneed -= c2;
    cgt   += c2;
    const uint32_t top24 = (b1 << 12) | b2;
    __syncthreads();

    // ---- pass 3: low 8 bits (restricted to top24) ----
    for (int i = t; i < 256; i += NTHREADS) hist[i] = 0;
    __syncthreads();
#pragma unroll
    for (int i = 0; i < VEC; i++) {
        uint4 kk = k4[i * NTHREADS + t];
        if ((kk.x >> 8) == top24) atomicAdd(&hist[kk.x & 0xFF], 1);
        if ((kk.y >> 8) == top24) atomicAdd(&hist[kk.y & 0xFF], 1);
        if ((kk.z >> 8) == top24) atomicAdd(&hist[kk.z & 0xFF], 1);
        if ((kk.w >> 8) == top24) atomicAdd(&hist[kk.w & 0xFF], 1);
    }
    __syncthreads();
    select_bin<256>(hist, S, ctrl, kneed);
    const uint32_t b3 = (uint32_t)ctrl[0];
    const int c3     = ctrl[1];
    const int cnt_eq = ctrl[2];            // #elements exactly equal to T
    cgt += c3;
    const int needed_eq = K - cgt;         // how many ties belong in top-k (1..cnt_eq)
    const uint32_t T = (top24 << 8) | b3;  // exact k-th largest key

    // ---- deterministic tie-break: keep the needed_eq LOWEST column indices ----
    // (matches jax.lax.top_k tie order). Common case needed_eq == cnt_eq: keep all.
    int idx_cut = COLS;                    // keep every tie by default
    if (needed_eq < cnt_eq) {
        __syncthreads();                   // done with hist/S — reuse as tie list + counter
        if (t == 0) S[0] = 0;
        __syncthreads();
#pragma unroll
        for (int i = 0; i < VEC; i++) {
            uint4 kk = k4[i * NTHREADS + t];
            int base = 4 * (i * NTHREADS + t);
            if (kk.x == T) { int p = atomicAdd(&S[0], 1); if (p < 4096) hist[p] = base + 0; }
            if (kk.y == T) { int p = atomicAdd(&S[0], 1); if (p < 4096) hist[p] = base + 1; }
            if (kk.z == T) { int p = atomicAdd(&S[0], 1); if (p < 4096) hist[p] = base + 2; }
            if (kk.w == T) { int p = atomicAdd(&S[0], 1); if (p < 4096) hist[p] = base + 3; }
        }
        __syncthreads();
        int cnt = S[0] < 4096 ? S[0] : 4096;
        // rank-select: idx_cut = (needed_eq)-th smallest index (rank needed_eq-1)
        for (int e = t; e < cnt; e += NTHREADS) {
            int v = hist[e];
            int r = 0;
            for (int q = 0; q < cnt; q++) r += (hist[q] < v);
            if (r == needed_eq - 1) ctrl[3] = v;
        }
        __syncthreads();
        idx_cut = ctrl[3];
    }

    // ---- write pass: dense output, float4 stores, no atomics ----
    float4* outr = (float4*)(out + (size_t)row * COLS);
#pragma unroll
    for (int i = 0; i < VEC; i++) {
        uint4 kk = k4[i * NTHREADS + t];
        int base = 4 * (i * NTHREADS + t);
        float4 o;
        o.x = (kk.x > T || (kk.x == T && base + 0 <= idx_cut)) ? k2f(kk.x) : 0.0f;
        o.y = (kk.y > T || (kk.y == T && base + 1 <= idx_cut)) ? k2f(kk.y) : 0.0f;
        o.z = (kk.z > T || (kk.z == T && base + 2 <= idx_cut)) ? k2f(kk.z) : 0.0f;
        o.w = (kk.w > T || (kk.w == T && base + 3 <= idx_cut)) ? k2f(kk.w) : 0.0f;
        outr[i * NTHREADS + t] = o;
    }
}

extern "C" void kernel_launch(void* const* d_in, const int* in_sizes, int n_in,
                              void* d_out, int out_size) {
    const float* x  = (const float*)d_in[0];
    const int*   kp = (const int*)d_in[1];
    float*       out = (float*)d_out;

    const int rows = in_sizes[0] / COLS;
    const size_t smem = (size_t)COLS * 4 + 4096 * 4 + 512 * 4 + 16;

    cudaFuncSetAttribute(topk_scatter_kernel,
                         cudaFuncAttributeMaxDynamicSharedMemorySize, (int)smem);
    topk_scatter_kernel<<<rows, NTHREADS, smem>>>(x, kp, out);
}

// round 3
// speedup vs baseline: 1.1910x; 1.1910x over previous
#include <cuda_runtime.h>
#include <stdint.h>

#define COLS 16384
#define NTHREADS 512
#define NWARPS (NTHREADS / 32)
#define VEC (COLS / 4 / NTHREADS)   // 8 float4 per thread
#define NBINS 1024                  // 10-bit radix
#define CAP 640                     // candidate list capacity

// Monotonic float->uint key transform (order-preserving)
__device__ __forceinline__ uint32_t f2k(float f) {
    uint32_t u = __float_as_uint(f);
    return u ^ ((uint32_t)((int32_t)u >> 31) | 0x80000000u);
}
__device__ __forceinline__ float k2f(uint32_t k) {
    uint32_t mask = (~((uint32_t)((int32_t)k >> 31))) | 0x80000000u;
    return __uint_as_float(k ^ mask);
}

// Find highest bin b such that count(bins > b) < kneed <= count(bins >= b).
// hist[NBINS] valid on entry. ctrl[0]=b, ctrl[1]=count strictly above b, ctrl[2]=hist[b].
// Shfl-based suffix scan: 2 barriers + final barrier.
__device__ void select_bin(const int* hist, int* warpbuf, int* ctrl, int kneed) {
    const int CH = NBINS / NTHREADS;   // 2
    int t = threadIdx.x, lane = t & 31, w = t >> 5;
    int h[CH];
    int cs = 0;
#pragma unroll
    for (int j = 0; j < CH; j++) { h[j] = hist[t * CH + j]; cs += h[j]; }
    // warp inclusive suffix scan (lane i -> sum of lanes i..31)
    int s = cs;
#pragma unroll
    for (int off = 1; off < 32; off <<= 1) {
        int v = __shfl_down_sync(0xffffffffu, s, off);
        if (lane + off < 32) s += v;
    }
    if (lane == 0) warpbuf[w] = s;     // warp total
    __syncthreads();
    if (w == 0) {
        int wt = (lane < NWARPS) ? warpbuf[lane] : 0;
        int ws = wt;
#pragma unroll
        for (int off = 1; off < 32; off <<= 1) {
            int v = __shfl_down_sync(0xffffffffu, ws, off);
            if (lane + off < 32) ws += v;
        }
        if (lane < NWARPS) warpbuf[lane] = ws;   // suffix over warps >= lane
    }
    __syncthreads();
    int above = (w < NWARPS - 1) ? warpbuf[w + 1] : 0;
    int S_incl = s + above;            // suffix including own chunk
    int S_next = S_incl - cs;          // suffix strictly after own chunk
    if (S_incl >= kneed && S_next < kneed) {
        int c = S_next;
#pragma unroll
        for (int j = CH - 1; j >= 0; j--) {
            if (c + h[j] >= kneed) { ctrl[0] = t * CH + j; ctrl[1] = c; ctrl[2] = h[j]; break; }
            c += h[j];
        }
    }
    __syncthreads();
}

__global__ void __launch_bounds__(NTHREADS, 3)
topk_scatter_kernel(const float* __restrict__ x, const int* __restrict__ kp,
                    float* __restrict__ out) {
    extern __shared__ uint8_t sm[];
    uint32_t* keys   = (uint32_t*)sm;                       // 64 KB
    int*      hist   = (int*)(sm + COLS * 4);               // 4 KB (shared by all passes)
    int*      cand   = hist + NBINS;                        // 2.5 KB
    int*      warpbuf= cand + CAP;                          // 64 B
    int*      ctrl   = warpbuf + NWARPS;                    // 32 B

    const int t   = threadIdx.x;
    const int row = blockIdx.x;
    const float4* xr = (const float4*)(x + (size_t)row * COLS);
    uint4* k4 = (uint4*)keys;

    // zero hist for pass 1
#pragma unroll
    for (int i = 0; i < NBINS / NTHREADS; i++) hist[t + i * NTHREADS] = 0;
    if (t == 0) { ctrl[4] = 0; }
    __syncthreads();

    // ---- load row, transform, store keys, AND histogram top 10 bits (from regs) ----
#pragma unroll
    for (int i = 0; i < VEC; i++) {
        float4 v = xr[i * NTHREADS + t];
        uint4 kk;
        kk.x = f2k(v.x); kk.y = f2k(v.y); kk.z = f2k(v.z); kk.w = f2k(v.w);
        k4[i * NTHREADS + t] = kk;
        atomicAdd(&hist[kk.x >> 22], 1);
        atomicAdd(&hist[kk.y >> 22], 1);
        atomicAdd(&hist[kk.z >> 22], 1);
        atomicAdd(&hist[kk.w >> 22], 1);
    }
    const int K = *kp;
    __syncthreads();

    // ---- pass 1 select: top 10 bits ----
    select_bin(hist, warpbuf, ctrl, K);
    const uint32_t b1 = (uint32_t)ctrl[0];
    const int c1 = ctrl[1];
    const int cnt_b1 = ctrl[2];
    int kneed = K - c1;
    __syncthreads();     // ctrl consumed; hist about to be reused

    // zero hist for pass 2
#pragma unroll
    for (int i = 0; i < NBINS / NTHREADS; i++) hist[t + i * NTHREADS] = 0;
    __syncthreads();

    // ---- gather sweep: candidates (top10 == b1) -> cand list + pass-2 histogram ----
#pragma unroll
    for (int i = 0; i < VEC; i++) {
        uint4 kk = k4[i * NTHREADS + t];
        if ((kk.x >> 22) == b1) { atomicAdd(&hist[(kk.x >> 12) & 0x3FF], 1); int p = atomicAdd(&ctrl[4], 1); if (p < CAP) cand[p] = (int)kk.x; }
        if ((kk.y >> 22) == b1) { atomicAdd(&hist[(kk.y >> 12) & 0x3FF], 1); int p = atomicAdd(&ctrl[4], 1); if (p < CAP) cand[p] = (int)kk.y; }
        if ((kk.z >> 22) == b1) { atomicAdd(&hist[(kk.z >> 12) & 0x3FF], 1); int p = atomicAdd(&ctrl[4], 1); if (p < CAP) cand[p] = (int)kk.z; }
        if ((kk.w >> 22) == b1) { atomicAdd(&hist[(kk.w >> 12) & 0x3FF], 1); int p = atomicAdd(&ctrl[4], 1); if (p < CAP) cand[p] = (int)kk.w; }
    }
    __syncthreads();
    const bool use_full = (ctrl[4] > CAP);    // pathological fallback
    const int cnt = use_full ? 0 : ctrl[4];
    (void)cnt_b1;

    // ---- pass 2 select: bits [21:12] ----
    select_bin(hist, warpbuf, ctrl, kneed);
    const uint32_t b2 = (uint32_t)ctrl[0];
    kneed -= ctrl[1];
    const uint32_t top20 = (b1 << 10) | b2;
    __syncthreads();

    // zero hist for pass 3
#pragma unroll
    for (int i = 0; i < NBINS / NTHREADS; i++) hist[t + i * NTHREADS] = 0;
    __syncthreads();

    // ---- pass 3 histogram: bits [11:2] over candidates (or full fallback) ----
    if (!use_full) {
        for (int e = t; e < cnt; e += NTHREADS) {
            uint32_t key = (uint32_t)cand[e];
            if ((key >> 12) == top20) atomicAdd(&hist[(key >> 2) & 0x3FF], 1);
        }
    } else {
#pragma unroll
        for (int i = 0; i < VEC; i++) {
            uint4 kk = k4[i * NTHREADS + t];
            if ((kk.x >> 12) == top20) atomicAdd(&hist[(kk.x >> 2) & 0x3FF], 1);
            if ((kk.y >> 12) == top20) atomicAdd(&hist[(kk.y >> 2) & 0x3FF], 1);
            if ((kk.z >> 12) == top20) atomicAdd(&hist[(kk.z >> 2) & 0x3FF], 1);
            if ((kk.w >> 12) == top20) atomicAdd(&hist[(kk.w >> 2) & 0x3FF], 1);
        }
    }
    __syncthreads();
    select_bin(hist, warpbuf, ctrl, kneed);
    const uint32_t b3 = (uint32_t)ctrl[0];
    kneed -= ctrl[1];
    const uint32_t top30 = (top20 << 10) | b3;
    __syncthreads();

    // ---- pass 4: final 2 bits (4 bins) ----
    if (t < 4) hist[t] = 0;
    __syncthreads();
    if (!use_full) {
        for (int e = t; e < cnt; e += NTHREADS) {
            uint32_t key = (uint32_t)cand[e];
            if ((key >> 2) == top30) atomicAdd(&hist[key & 3], 1);
        }
    } else {
#pragma unroll
        for (int i = 0; i < VEC; i++) {
            uint4 kk = k4[i * NTHREADS + t];
            if ((kk.x >> 2) == top30) atomicAdd(&hist[kk.x & 3], 1);
            if ((kk.y >> 2) == top30) atomicAdd(&hist[kk.y & 3], 1);
            if ((kk.z >> 2) == top30) atomicAdd(&hist[kk.z & 3], 1);
            if ((kk.w >> 2) == top30) atomicAdd(&hist[kk.w & 3], 1);
        }
    }
    __syncthreads();
    if (t == 0) {
        int c = 0;
        for (int b = 3; b >= 0; b--) {
            int h = hist[b];
            if (c + h >= kneed) { ctrl[0] = b; ctrl[1] = c; ctrl[2] = h; break; }
            c += h;
        }
    }
    __syncthreads();
    const uint32_t b4 = (uint32_t)ctrl[0];
    const int cnt_eq = ctrl[2];
    const int needed_eq = kneed - ctrl[1];       // ties that belong in top-k
    const uint32_t T = (top30 << 2) | b4;        // exact k-th largest key

    // ---- deterministic tie-break (rare): keep the needed_eq LOWEST column indices ----
    int idx_cut = COLS;
    if (needed_eq < cnt_eq) {
        __syncthreads();
        if (t == 0) ctrl[5] = 0;
        __syncthreads();
#pragma unroll
        for (int i = 0; i < VEC; i++) {
            uint4 kk = k4[i * NTHREADS + t];
            int base = 4 * (i * NTHREADS + t);
            if (kk.x == T) { int p = atomicAdd(&ctrl[5], 1); if (p < CAP) cand[p] = base + 0; }
            if (kk.y == T) { int p = atomicAdd(&ctrl[5], 1); if (p < CAP) cand[p] = base + 1; }
            if (kk.z == T) { int p = atomicAdd(&ctrl[5], 1); if (p < CAP) cand[p] = base + 2; }
            if (kk.w == T) { int p = atomicAdd(&ctrl[5], 1); if (p < CAP) cand[p] = base + 3; }
        }
        __syncthreads();
        int tc = ctrl[5] < CAP ? ctrl[5] : CAP;
        for (int e = t; e < tc; e += NTHREADS) {
            int v = cand[e];
            int r = 0;
            for (int q = 0; q < tc; q++) r += (cand[q] < v);
            if (r == needed_eq - 1) ctrl[3] = v;
        }
        __syncthreads();
        idx_cut = ctrl[3];
    }

    // ---- write pass: dense output, float4 streaming stores ----
    float4* outr = (float4*)(out + (size_t)row * COLS);
#pragma unroll
    for (int i = 0; i < VEC; i++) {
        uint4 kk = k4[i * NTHREADS + t];
        int base = 4 * (i * NTHREADS + t);
        float4 o;
        o.x = (kk.x > T || (kk.x == T && base + 0 <= idx_cut)) ? k2f(kk.x) : 0.0f;
        o.y = (kk.y > T || (kk.y == T && base + 1 <= idx_cut)) ? k2f(kk.y) : 0.0f;
        o.z = (kk.z > T || (kk.z == T && base + 2 <= idx_cut)) ? k2f(kk.z) : 0.0f;
        o.w = (kk.w > T || (kk.w == T && base + 3 <= idx_cut)) ? k2f(kk.w) : 0.0f;
        __stcs(&outr[i * NTHREADS + t], o);
    }
}

extern "C" void kernel_launch(void* const* d_in, const int* in_sizes, int n_in,
                              void* d_out, int out_size) {
    const float* x  = (const float*)d_in[0];
    const int*   kp = (const int*)d_in[1];
    float*       out = (float*)d_out;

    const int rows = in_sizes[0] / COLS;
    const size_t smem = (size_t)COLS * 4 + NBINS * 4 + CAP * 4 + NWARPS * 4 + 8 * 4;

    cudaFuncSetAttribute(topk_scatter_kernel,
                         cudaFuncAttributeMaxDynamicSharedMemorySize, (int)smem);
    topk_scatter_kernel<<<rows, NTHREADS, smem>>>(x, kp, out);
}